// round 2
// baseline (speedup 1.0000x reference)
#include <cuda_runtime.h>
#include <math.h>

#define NBATCH 8
#define NPTS   131072
#define NGRP   30
#define NGB    (NBATCH*NGRP)   // 240
#define KNN    100
#define STRIDE 4369            // 131072/30
#define NT     256
#define HB     2048            // float-radix bins: bits(d2) >> 21
#define TIECAP 1024

// global scratch (no allocation allowed)
__device__ double d_gmean[NGB][3];
__device__ double d_gcov[NGB][6];

struct Sm {
    unsigned hist[HB];
    unsigned partial[NT];
    float    tieD[TIECAP];
    int      tieI[TIECAP];
    float    tieP[TIECAP][3];
    double   red[NT];
    double   acc[9];      // sx,sy,sz, sxx,sxy,sxz,syy,syz,szz
    double   qnew[3];
    unsigned ntie;
    int      pivot;
    int      mneed;
};

__global__ void __launch_bounds__(NT) knn_kernel(const float* __restrict__ pts_all) {
    __shared__ Sm sm;
    const int tid = threadIdx.x;
    const int gb  = blockIdx.x;
    const int b   = gb / NGRP;
    const int g   = gb % NGRP;
    const float* __restrict__ pts = pts_all + (size_t)b * NPTS * 3;

    const int ci = g * STRIDE;
    float qx = pts[3*ci + 0];
    float qy = pts[3*ci + 1];
    float qz = pts[3*ci + 2];

    for (int pass = 0; pass < 2; pass++) {
        // ---- scan 1: histogram of d2 ----
        for (int i = tid; i < HB; i += NT) sm.hist[i] = 0u;
        if (tid == 0) sm.ntie = 0u;
        __syncthreads();

        for (int i = tid; i < NPTS; i += NT) {
            float x = pts[3*i+0], y = pts[3*i+1], z = pts[3*i+2];
            float dx = x - qx, dy = y - qy, dz = z - qz;
            float d2 = fmaf(dx, dx, fmaf(dy, dy, dz*dz));
            atomicAdd(&sm.hist[__float_as_uint(d2) >> 21], 1u);
        }
        __syncthreads();

        // ---- find pivot bin: cum count crosses KNN ----
        {
            unsigned ps = 0;
            #pragma unroll
            for (int j = 0; j < HB/NT; j++) ps += sm.hist[tid*(HB/NT) + j];
            sm.partial[tid] = ps;
        }
        __syncthreads();
        if (tid == 0) {
            unsigned c = 0; int t = 0;
            while (c + sm.partial[t] < KNN) { c += sm.partial[t]; t++; }
            int bin = t * (HB/NT);
            while (c + sm.hist[bin] < KNN) { c += sm.hist[bin]; bin++; }
            sm.pivot = bin;
            sm.mneed = KNN - (int)c;
        }
        __syncthreads();
        const int pivot = sm.pivot;
        const int m     = sm.mneed;

        // ---- scan 2: accumulate sure winners (bin<pivot), collect ties ----
        double a0=0,a1=0,a2=0,a3=0,a4=0,a5=0,a6=0,a7=0,a8=0;
        for (int i = tid; i < NPTS; i += NT) {
            float x = pts[3*i+0], y = pts[3*i+1], z = pts[3*i+2];
            float dx = x - qx, dy = y - qy, dz = z - qz;
            float d2 = fmaf(dx, dx, fmaf(dy, dy, dz*dz));
            int bin = (int)(__float_as_uint(d2) >> 21);
            if (bin < pivot) {
                double X = x, Y = y, Z = z;
                a0 += X; a1 += Y; a2 += Z;
                a3 += X*X; a4 += X*Y; a5 += X*Z;
                a6 += Y*Y; a7 += Y*Z; a8 += Z*Z;
            } else if (bin == pivot) {
                unsigned p = atomicAdd(&sm.ntie, 1u);
                if (p < TIECAP) {
                    sm.tieD[p] = d2; sm.tieI[p] = i;
                    sm.tieP[p][0] = x; sm.tieP[p][1] = y; sm.tieP[p][2] = z;
                }
            }
        }

        // fixed-order tree reduction of the 9 accumulators (deterministic)
        double av[9] = {a0,a1,a2,a3,a4,a5,a6,a7,a8};
        for (int k = 0; k < 9; k++) {
            __syncthreads();
            sm.red[tid] = av[k];
            __syncthreads();
            for (int s = NT/2; s > 0; s >>= 1) {
                if (tid < s) sm.red[tid] += sm.red[tid + s];
                __syncthreads();
            }
            if (tid == 0) sm.acc[k] = sm.red[0];
        }
        __syncthreads();

        // ---- tid 0: resolve ties in exact (d2, idx) ascending order ----
        if (tid == 0) {
            int ntie = (int)min(sm.ntie, (unsigned)TIECAP);
            unsigned usedw[TIECAP/32];
            for (int w = 0; w < TIECAP/32; w++) usedw[w] = 0u;
            for (int r = 0; r < m; r++) {
                int best = -1; float bd = 0.f; int bi = 0;
                for (int t2 = 0; t2 < ntie; t2++) {
                    if ((usedw[t2>>5] >> (t2 & 31)) & 1u) continue;
                    float d = sm.tieD[t2]; int ii = sm.tieI[t2];
                    if (best < 0 || d < bd || (d == bd && ii < bi)) { best = t2; bd = d; bi = ii; }
                }
                if (best < 0) break;
                usedw[best>>5] |= (1u << (best & 31));
                double X = sm.tieP[best][0], Y = sm.tieP[best][1], Z = sm.tieP[best][2];
                sm.acc[0] += X; sm.acc[1] += Y; sm.acc[2] += Z;
                sm.acc[3] += X*X; sm.acc[4] += X*Y; sm.acc[5] += X*Z;
                sm.acc[6] += Y*Y; sm.acc[7] += Y*Z; sm.acc[8] += Z*Z;
            }
            const double K = (double)KNN;
            double mx = sm.acc[0]/K, my = sm.acc[1]/K, mz = sm.acc[2]/K;
            if (pass == 0) {
                d_gmean[gb][0] = mx; d_gmean[gb][1] = my; d_gmean[gb][2] = mz;
                sm.qnew[0] = mx; sm.qnew[1] = my; sm.qnew[2] = mz;
            } else {
                d_gcov[gb][0] = sm.acc[3]/K - mx*mx;
                d_gcov[gb][1] = sm.acc[4]/K - mx*my;
                d_gcov[gb][2] = sm.acc[5]/K - mx*mz;
                d_gcov[gb][3] = sm.acc[6]/K - my*my;
                d_gcov[gb][4] = sm.acc[7]/K - my*mz;
                d_gcov[gb][5] = sm.acc[8]/K - mz*mz;
            }
        }
        __syncthreads();
        if (pass == 0) {
            qx = (float)sm.qnew[0];
            qy = (float)sm.qnew[1];
            qz = (float)sm.qnew[2];
        }
        __syncthreads();
    }
}

__global__ void __launch_bounds__(256) fin_kernel(float* __restrict__ out) {
    __shared__ float  dirs[NGB][3];
    __shared__ float  gmf[NGB][3];
    __shared__ double redd[256];
    const int t = threadIdx.x;

    double fs = 0.0;
    if (t < NGB) {
        double a00 = d_gcov[t][0], a01 = d_gcov[t][1], a02 = d_gcov[t][2];
        double a11 = d_gcov[t][3], a12 = d_gcov[t][4], a22 = d_gcov[t][5];

        double q  = (a00 + a11 + a22) / 3.0;
        double p1 = a01*a01 + a02*a02 + a12*a12;
        double b00 = a00 - q, b11 = a11 - q, b22 = a22 - q;
        double p2 = b00*b00 + b11*b11 + b22*b22 + 2.0*p1;
        double l1, l2, l3;
        if (p2 < 1e-60) {
            l1 = l2 = l3 = q;
        } else {
            double p  = sqrt(p2 / 6.0);
            double ip = 1.0 / p;
            double c00 = b00*ip, c11 = b11*ip, c22 = b22*ip;
            double c01 = a01*ip, c02 = a02*ip, c12 = a12*ip;
            double detB = c00*(c11*c22 - c12*c12)
                        - c01*(c01*c22 - c12*c02)
                        + c02*(c01*c12 - c11*c02);
            double r = 0.5 * detB;
            r = fmin(1.0, fmax(-1.0, r));
            double phi = acos(r) / 3.0;
            l3 = q + 2.0*p*cos(phi);
            l1 = q + 2.0*p*cos(phi + 2.0943951023931953);  // +2pi/3 -> smallest
            l2 = 3.0*q - l1 - l3;
        }
        double denom = l1 + l2 + l3 + 1e-9;
        fs = (l3 - l2) / denom;

        // eigenvector for l3: null space of (A - l3 I) via best row cross-product
        double r0x = a00 - l3, r0y = a01,      r0z = a02;
        double r1x = a01,      r1y = a11 - l3, r1z = a12;
        double r2x = a02,      r2y = a12,      r2z = a22 - l3;
        double vax = r0y*r1z - r0z*r1y, vay = r0z*r1x - r0x*r1z, vaz = r0x*r1y - r0y*r1x;
        double vbx = r1y*r2z - r1z*r2y, vby = r1z*r2x - r1x*r2z, vbz = r1x*r2y - r1y*r2x;
        double vcx = r2y*r0z - r2z*r0y, vcy = r2z*r0x - r2x*r0z, vcz = r2x*r0y - r2y*r0x;
        double na = vax*vax + vay*vay + vaz*vaz;
        double nb = vbx*vbx + vby*vby + vbz*vbz;
        double nc = vcx*vcx + vcy*vcy + vcz*vcz;
        double vx, vy, vz, nn;
        if (na >= nb && na >= nc) { vx = vax; vy = vay; vz = vaz; nn = na; }
        else if (nb >= nc)        { vx = vbx; vy = vby; vz = vbz; nn = nb; }
        else                      { vx = vcx; vy = vcy; vz = vcz; nn = nc; }
        if (nn < 1e-300) { vx = 0.0; vy = 0.0; vz = 1.0; nn = 1.0; }
        double inn = rsqrt(nn);
        dirs[t][0] = (float)(vx * inn);
        dirs[t][1] = (float)(vy * inn);
        dirs[t][2] = (float)(vz * inn);
        gmf[t][0] = (float)d_gmean[t][0];
        gmf[t][1] = (float)d_gmean[t][1];
        gmf[t][2] = (float)d_gmean[t][2];
    }
    __syncthreads();

    double term = 0.0;
    if (t < NGB) {
        int b = t / NGRP, g = t % NGRP;
        float qx = gmf[t][0], qy = gmf[t][1], qz = gmf[t][2];
        float best = 3.4e38f; int bj = 0;
        for (int o = 0; o < NGRP; o++) {
            float dx = qx - gmf[b*NGRP+o][0];
            float dy = qy - gmf[b*NGRP+o][1];
            float dz = qz - gmf[b*NGRP+o][2];
            float dd = dx*dx + dy*dy + dz*dz;
            if (o == g) dd += 1e30f;
            if (dd < best) { best = dd; bj = o; }
        }
        int j = b*NGRP + bj;
        float cs = dirs[t][0]*dirs[j][0] + dirs[t][1]*dirs[j][1] + dirs[t][2]*dirs[j][2];
        term = 1.0 - (double)cs * (double)cs;
    }

    // deterministic tree reductions
    redd[t] = fs;
    __syncthreads();
    for (int s = 128; s > 0; s >>= 1) { if (t < s) redd[t] += redd[t+s]; __syncthreads(); }
    double sumfs = redd[0];
    __syncthreads();
    redd[t] = term;
    __syncthreads();
    for (int s = 128; s > 0; s >>= 1) { if (t < s) redd[t] += redd[t+s]; __syncthreads(); }
    double sumterm = redd[0];

    if (t == 0) out[0] = (float)(-sumfs / (double)NBATCH + sumterm / (double)NGB);
}

extern "C" void kernel_launch(void* const* d_in, const int* in_sizes, int n_in,
                              void* d_out, int out_size) {
    const float* pts = (const float*)d_in[0];
    float* out = (float*)d_out;
    knn_kernel<<<NGB, NT>>>(pts);
    fin_kernel<<<1, 256>>>(out);
}

// round 3
// speedup vs baseline: 3.4817x; 3.4817x over previous
#include <cuda_runtime.h>
#include <math.h>

#define NBATCH 8
#define NPTS   131072
#define NGRP   30
#define NGB    (NBATCH*NGRP)   // 240
#define KNN    100
#define STRIDE 4369            // 131072/30
#define NT     256
#define HB     2048            // float-radix bins: bits(d2) >> 21
#define CAP    6144            // pass-2 candidate cap
#define SCAP   512             // selection subset cap
#define DYNSMEM (4*CAP*4)      // cx,cy,cz,ci

__device__ double d_gmean[NGB][3];
__device__ double d_gcov[NGB][6];

__device__ __forceinline__ unsigned d2bin(float d2) {
    return __float_as_uint(d2) >> 21;
}

__global__ void __launch_bounds__(NT, 2) knn_kernel(const float* __restrict__ pts_all) {
    extern __shared__ float dyn[];
    float* cX = dyn;
    float* cY = cX + CAP;
    float* cZ = cY + CAP;
    int*   cI = (int*)(cZ + CAP);

    __shared__ unsigned hist[HB];
    __shared__ unsigned partial[NT];
    __shared__ float    subD[SCAP];
    __shared__ int      subI[SCAP];
    __shared__ int      subSlot[SCAP];
    __shared__ int      order[KNN];
    __shared__ unsigned ncand, nsub;
    __shared__ int      pivotS;
    __shared__ float    bc[6];   // qx2,qy2,qz2,T2

    const int tid = threadIdx.x;
    const int gb  = blockIdx.x;
    const int b   = gb / NGRP;
    const int g   = gb % NGRP;
    const float* __restrict__ pts = pts_all + (size_t)b * NPTS * 3;
    const float4* __restrict__ p4 = (const float4*)pts;

    const int c0 = g * STRIDE;
    const float qx = pts[3*c0+0], qy = pts[3*c0+1], qz = pts[3*c0+2];

    // ================= scan 1: histogram of d2 to center =================
    for (int i = tid; i < HB; i += NT) hist[i] = 0u;
    __syncthreads();

    #pragma unroll 2
    for (int it = tid; it < NPTS/4; it += NT) {
        float4 A = p4[3*it+0];
        float4 B = p4[3*it+1];
        float4 C = p4[3*it+2];
        float xs[4] = {A.x, A.w, B.z, C.y};
        float ys[4] = {A.y, B.x, B.w, C.z};
        float zs[4] = {A.z, B.y, C.x, C.w};
        #pragma unroll
        for (int k = 0; k < 4; k++) {
            float dx = xs[k]-qx, dy = ys[k]-qy, dz = zs[k]-qz;
            float d2 = fmaf(dx, dx, fmaf(dy, dy, dz*dz));
            atomicAdd(&hist[d2bin(d2)], 1u);
        }
    }
    __syncthreads();

    // pivot bin (cum count crosses KNN)
    {
        unsigned ps = 0;
        #pragma unroll
        for (int j = 0; j < HB/NT; j++) ps += hist[tid*(HB/NT) + j];
        partial[tid] = ps;
    }
    __syncthreads();
    if (tid == 0) {
        unsigned c = 0; int t = 0;
        while (c + partial[t] < KNN) { c += partial[t]; t++; }
        int bin = t * (HB/NT);
        while (c + hist[bin] < KNN) { c += hist[bin]; bin++; }
        pivotS = bin;
    }
    __syncthreads();
    const float edge1 = __uint_as_float(((unsigned)pivotS + 1u) << 21);  // > d_100

    // ====== scan 2: collect C1 = {d2 < edge1}  (~K + pivot-bin ties) ======
    if (tid == 0) ncand = 0u;
    __syncthreads();
    #pragma unroll 2
    for (int it = tid; it < NPTS/4; it += NT) {
        float4 A = p4[3*it+0];
        float4 B = p4[3*it+1];
        float4 C = p4[3*it+2];
        float xs[4] = {A.x, A.w, B.z, C.y};
        float ys[4] = {A.y, B.x, B.w, C.z};
        float zs[4] = {A.z, B.y, C.x, C.w};
        #pragma unroll
        for (int k = 0; k < 4; k++) {
            float dx = xs[k]-qx, dy = ys[k]-qy, dz = zs[k]-qz;
            float d2 = fmaf(dx, dx, fmaf(dy, dy, dz*dz));
            if (d2 < edge1) {
                unsigned s = atomicAdd(&ncand, 1u);
                if (s < SCAP) {
                    cX[s] = xs[k]; cY[s] = ys[k]; cZ[s] = zs[k];
                    subD[s] = d2; subI[s] = 4*it + k;
                }
            }
        }
    }
    __syncthreads();

    // ---- pass-1 exact top-K by (d2, idx) rank over C1 ----
    {
        int S = (int)min(ncand, (unsigned)SCAP);
        for (int s = tid; s < S; s += NT) {
            float d = subD[s]; int id = subI[s];
            int rank = 0;
            for (int j = 0; j < S; j++) {
                float dj = subD[j];
                rank += (dj < d) || (dj == d && subI[j] < id);
            }
            if (rank < KNN) order[rank] = s;
        }
    }
    __syncthreads();
    if (tid == 0) {
        double sx = 0.0, sy = 0.0, sz = 0.0;
        for (int r = 0; r < KNN; r++) {
            int s = order[r];
            sx += (double)cX[s]; sy += (double)cY[s]; sz += (double)cZ[s];
        }
        double mx = sx/(double)KNN, my = sy/(double)KNN, mz = sz/(double)KNN;
        d_gmean[gb][0] = mx; d_gmean[gb][1] = my; d_gmean[gb][2] = mz;
        float fmx = (float)mx, fmy = (float)my, fmz = (float)mz;
        double dxq = mx - (double)qx, dyq = my - (double)qy, dzq = mz - (double)qz;
        double D  = sqrt(dxq*dxq + dyq*dyq + dzq*dzq);
        double r1 = sqrt((double)edge1);
        double R  = 2.0*D + r1;
        bc[0] = fmx; bc[1] = fmy; bc[2] = fmz;
        bc[3] = (float)(R*R) * 1.0002f;
    }
    __syncthreads();
    const float q2x = bc[0], q2y = bc[1], q2z = bc[2];
    const float T2  = bc[3];

    // ====== scan 3: collect C2 = {d2_center < T2}  (covers pass-2 ball) ======
    if (tid == 0) ncand = 0u;
    __syncthreads();
    #pragma unroll 2
    for (int it = tid; it < NPTS/4; it += NT) {
        float4 A = p4[3*it+0];
        float4 B = p4[3*it+1];
        float4 C = p4[3*it+2];
        float xs[4] = {A.x, A.w, B.z, C.y};
        float ys[4] = {A.y, B.x, B.w, C.z};
        float zs[4] = {A.z, B.y, C.x, C.w};
        #pragma unroll
        for (int k = 0; k < 4; k++) {
            float dx = xs[k]-qx, dy = ys[k]-qy, dz = zs[k]-qz;
            float d2 = fmaf(dx, dx, fmaf(dy, dy, dz*dz));
            if (d2 < T2) {
                unsigned s = atomicAdd(&ncand, 1u);
                if (s < CAP) {
                    cX[s] = xs[k]; cY[s] = ys[k]; cZ[s] = zs[k];
                    cI[s] = 4*it + k;
                }
            }
        }
    }
    __syncthreads();
    const int C2 = (int)min(ncand, (unsigned)CAP);

    // ---- pass-2 selection vs mean query, all in smem ----
    for (int i = tid; i < HB; i += NT) hist[i] = 0u;
    __syncthreads();
    for (int c = tid; c < C2; c += NT) {
        float dx = cX[c]-q2x, dy = cY[c]-q2y, dz = cZ[c]-q2z;
        float d2 = fmaf(dx, dx, fmaf(dy, dy, dz*dz));
        atomicAdd(&hist[d2bin(d2)], 1u);
    }
    __syncthreads();
    {
        unsigned ps = 0;
        #pragma unroll
        for (int j = 0; j < HB/NT; j++) ps += hist[tid*(HB/NT) + j];
        partial[tid] = ps;
    }
    __syncthreads();
    if (tid == 0) {
        unsigned c = 0; int t = 0;
        while (c + partial[t] < KNN) { c += partial[t]; t++; }
        int bin = t * (HB/NT);
        while (c + hist[bin] < KNN) { c += hist[bin]; bin++; }
        pivotS = bin;
        nsub = 0u;
    }
    __syncthreads();
    const unsigned piv2 = (unsigned)pivotS;
    for (int c = tid; c < C2; c += NT) {
        float dx = cX[c]-q2x, dy = cY[c]-q2y, dz = cZ[c]-q2z;
        float d2 = fmaf(dx, dx, fmaf(dy, dy, dz*dz));
        if (d2bin(d2) <= piv2) {
            unsigned s = atomicAdd(&nsub, 1u);
            if (s < SCAP) { subD[s] = d2; subI[s] = cI[c]; subSlot[s] = c; }
        }
    }
    __syncthreads();
    {
        int S = (int)min(nsub, (unsigned)SCAP);
        for (int s = tid; s < S; s += NT) {
            float d = subD[s]; int id = subI[s];
            int rank = 0;
            for (int j = 0; j < S; j++) {
                float dj = subD[j];
                rank += (dj < d) || (dj == d && subI[j] < id);
            }
            if (rank < KNN) order[rank] = subSlot[s];
        }
    }
    __syncthreads();
    if (tid == 0) {
        double s0=0,s1=0,s2=0,s3=0,s4=0,s5=0,s6=0,s7=0,s8=0;
        for (int r = 0; r < KNN; r++) {
            int c = order[r];
            double X = (double)cX[c], Y = (double)cY[c], Z = (double)cZ[c];
            s0 += X; s1 += Y; s2 += Z;
            s3 += X*X; s4 += X*Y; s5 += X*Z;
            s6 += Y*Y; s7 += Y*Z; s8 += Z*Z;
        }
        const double K = (double)KNN;
        double mx = s0/K, my = s1/K, mz = s2/K;
        d_gcov[gb][0] = s3/K - mx*mx;
        d_gcov[gb][1] = s4/K - mx*my;
        d_gcov[gb][2] = s5/K - mx*mz;
        d_gcov[gb][3] = s6/K - my*my;
        d_gcov[gb][4] = s7/K - my*mz;
        d_gcov[gb][5] = s8/K - mz*mz;
    }
}

__global__ void __launch_bounds__(256) fin_kernel(float* __restrict__ out) {
    __shared__ float  dirs[NGB][3];
    __shared__ float  gmf[NGB][3];
    __shared__ double redd[256];
    const int t = threadIdx.x;

    double fs = 0.0;
    if (t < NGB) {
        double a00 = d_gcov[t][0], a01 = d_gcov[t][1], a02 = d_gcov[t][2];
        double a11 = d_gcov[t][3], a12 = d_gcov[t][4], a22 = d_gcov[t][5];

        double q  = (a00 + a11 + a22) / 3.0;
        double p1 = a01*a01 + a02*a02 + a12*a12;
        double b00 = a00 - q, b11 = a11 - q, b22 = a22 - q;
        double p2 = b00*b00 + b11*b11 + b22*b22 + 2.0*p1;
        double l1, l2, l3;
        if (p2 < 1e-60) {
            l1 = l2 = l3 = q;
        } else {
            double p  = sqrt(p2 / 6.0);
            double ip = 1.0 / p;
            double c00 = b00*ip, c11 = b11*ip, c22 = b22*ip;
            double c01 = a01*ip, c02 = a02*ip, c12 = a12*ip;
            double detB = c00*(c11*c22 - c12*c12)
                        - c01*(c01*c22 - c12*c02)
                        + c02*(c01*c12 - c11*c02);
            double r = 0.5 * detB;
            r = fmin(1.0, fmax(-1.0, r));
            // float transcendentals inside double arithmetic: phi error ~1e-7,
            // eigenvalue error ~p*1e-7 << eigen gap. No FP64 MUFU on sm_103a.
            double phi = (double)acosf((float)r) * (1.0/3.0);
            l3 = q + 2.0*p*(double)cosf((float)phi);
            l1 = q + 2.0*p*(double)cosf((float)(phi + 2.0943951023931953));
            l2 = 3.0*q - l1 - l3;
        }
        double denom = l1 + l2 + l3 + 1e-9;
        fs = (l3 - l2) / denom;

        double r0x = a00 - l3, r0y = a01,      r0z = a02;
        double r1x = a01,      r1y = a11 - l3, r1z = a12;
        double r2x = a02,      r2y = a12,      r2z = a22 - l3;
        double vax = r0y*r1z - r0z*r1y, vay = r0z*r1x - r0x*r1z, vaz = r0x*r1y - r0y*r1x;
        double vbx = r1y*r2z - r1z*r2y, vby = r1z*r2x - r1x*r2z, vbz = r1x*r2y - r1y*r2x;
        double vcx = r2y*r0z - r2z*r0y, vcy = r2z*r0x - r2x*r0z, vcz = r2x*r0y - r2y*r0x;
        double na = vax*vax + vay*vay + vaz*vaz;
        double nb = vbx*vbx + vby*vby + vbz*vbz;
        double nc = vcx*vcx + vcy*vcy + vcz*vcz;
        double vx, vy, vz, nn;
        if (na >= nb && na >= nc) { vx = vax; vy = vay; vz = vaz; nn = na; }
        else if (nb >= nc)        { vx = vbx; vy = vby; vz = vbz; nn = nb; }
        else                      { vx = vcx; vy = vcy; vz = vcz; nn = nc; }
        if (nn < 1e-300) { vx = 0.0; vy = 0.0; vz = 1.0; nn = 1.0; }
        double inn = rsqrt(nn);
        dirs[t][0] = (float)(vx * inn);
        dirs[t][1] = (float)(vy * inn);
        dirs[t][2] = (float)(vz * inn);
        gmf[t][0] = (float)d_gmean[t][0];
        gmf[t][1] = (float)d_gmean[t][1];
        gmf[t][2] = (float)d_gmean[t][2];
    }
    __syncthreads();

    double term = 0.0;
    if (t < NGB) {
        int b = t / NGRP, g = t % NGRP;
        float qx = gmf[t][0], qy = gmf[t][1], qz = gmf[t][2];
        float best = 3.4e38f; int bj = 0;
        for (int o = 0; o < NGRP; o++) {
            float dx = qx - gmf[b*NGRP+o][0];
            float dy = qy - gmf[b*NGRP+o][1];
            float dz = qz - gmf[b*NGRP+o][2];
            float dd = dx*dx + dy*dy + dz*dz;
            if (o == g) dd += 1e30f;
            if (dd < best) { best = dd; bj = o; }
        }
        int j = b*NGRP + bj;
        float cs = dirs[t][0]*dirs[j][0] + dirs[t][1]*dirs[j][1] + dirs[t][2]*dirs[j][2];
        term = 1.0 - (double)cs * (double)cs;
    }

    redd[t] = fs;
    __syncthreads();
    for (int s = 128; s > 0; s >>= 1) { if (t < s) redd[t] += redd[t+s]; __syncthreads(); }
    double sumfs = redd[0];
    __syncthreads();
    redd[t] = term;
    __syncthreads();
    for (int s = 128; s > 0; s >>= 1) { if (t < s) redd[t] += redd[t+s]; __syncthreads(); }
    double sumterm = redd[0];

    if (t == 0) out[0] = (float)(-sumfs / (double)NBATCH + sumterm / (double)NGB);
}

extern "C" void kernel_launch(void* const* d_in, const int* in_sizes, int n_in,
                              void* d_out, int out_size) {
    const float* pts = (const float*)d_in[0];
    float* out = (float*)d_out;
    cudaFuncSetAttribute(knn_kernel, cudaFuncAttributeMaxDynamicSharedMemorySize, DYNSMEM);
    knn_kernel<<<NGB, NT, DYNSMEM>>>(pts);
    fin_kernel<<<1, 256>>>(out);
}